// round 1
// baseline (speedup 1.0000x reference)
#include <cuda_runtime.h>
#include <math.h>
#include <stdint.h>

#define NTOK   65586
#define MCLUS  50
#define NPATH  65536
#define DIM    256
#define SCALE  0.0625f   // D^-0.5 = 1/16

// ---------------- scratch (device globals; no allocation allowed) -----------
__device__ float g_qkv[(size_t)NTOK * 768];      // q|k|v per token row
__device__ float g_ocp[(size_t)NPATH * DIM];     // out_cross_path
__device__ float g_osc[MCLUS * DIM];             // out_self_celltypes
__device__ float g_occ[MCLUS * DIM];             // out_cross_celltypes
__device__ float g_ql[(size_t)NPATH * DIM];
__device__ float g_kl[(size_t)NPATH * DIM];
__device__ float g_klsum[DIM];
__device__ float g_kv[DIM * DIM];
__device__ float g_zfac[NPATH];
__device__ float g_spin[(size_t)NPATH * DIM];    // fm, then out_s+fm
__device__ float g_osp[(size_t)NPATH * DIM];     // out_self_path
__device__ float g_Acp[NPATH];
__device__ float g_Asp[NPATH];
__device__ float g_Acc[MCLUS];
__device__ float g_Asc[MCLUS];
__device__ float g_cacM[MCLUS * 16];
__device__ float g_cacL[MCLUS * 16];
__device__ float g_cacAcc[MCLUS * 16 * DIM];
__device__ float g_fmax[4];
__device__ float g_fl[4];
__device__ float g_fh[4 * DIM];

// ---------------- init: zero accumulators used with atomics -----------------
__global__ void init_kernel() {
    int t = threadIdx.x;
    for (int i = t; i < DIM * DIM; i += 256) g_kv[i] = 0.f;
    if (t < DIM) g_klsum[t] = 0.f;
    if (t < 4) g_fl[t] = 0.f;
    for (int i = t; i < 4 * DIM; i += 256) g_fh[i] = 0.f;
}

// ---------------- generic tiled fp32 GEMM: C = A(MxK) * B(KxN) --------------
// optional per-row scale (applied to product), optional += existing C, bias.
__global__ void gemm_kernel(const float* __restrict__ A, int lda,
                            const float* __restrict__ B, int ldb,
                            float* __restrict__ C, int ldc,
                            int Mr, int Nc, int Kd,
                            const float* __restrict__ bias,
                            const float* __restrict__ rowScale,
                            int addC)
{
    __shared__ float As[64][17];
    __shared__ float Bs[16][68];
    int tid = threadIdx.x;
    int tx = tid & 15, ty = tid >> 4;
    int row0 = blockIdx.y * 64;
    int col0 = blockIdx.x * 64;
    float acc[4][4];
#pragma unroll
    for (int i = 0; i < 4; i++)
#pragma unroll
        for (int j = 0; j < 4; j++) acc[i][j] = 0.f;

    int ar = tid >> 2;            // 0..63
    int ak = (tid & 3) * 4;       // 0,4,8,12
    int brow = tid >> 4;          // 0..15
    int bcol = (tid & 15) * 4;    // 0..60

    for (int k0 = 0; k0 < Kd; k0 += 16) {
        float4 av = make_float4(0.f, 0.f, 0.f, 0.f);
        if (row0 + ar < Mr)
            av = *(const float4*)&A[(size_t)(row0 + ar) * lda + k0 + ak];
        As[ar][ak + 0] = av.x; As[ar][ak + 1] = av.y;
        As[ar][ak + 2] = av.z; As[ar][ak + 3] = av.w;

        float4 bv = make_float4(0.f, 0.f, 0.f, 0.f);
        if (col0 + bcol < Nc)
            bv = *(const float4*)&B[(size_t)(k0 + brow) * ldb + col0 + bcol];
        Bs[brow][bcol + 0] = bv.x; Bs[brow][bcol + 1] = bv.y;
        Bs[brow][bcol + 2] = bv.z; Bs[brow][bcol + 3] = bv.w;
        __syncthreads();

#pragma unroll
        for (int kk = 0; kk < 16; kk++) {
            float ra[4], rb[4];
#pragma unroll
            for (int i = 0; i < 4; i++) ra[i] = As[ty * 4 + i][kk];
#pragma unroll
            for (int j = 0; j < 4; j++) rb[j] = Bs[kk][tx * 4 + j];
#pragma unroll
            for (int i = 0; i < 4; i++)
#pragma unroll
                for (int j = 0; j < 4; j++) acc[i][j] += ra[i] * rb[j];
        }
        __syncthreads();
    }

#pragma unroll
    for (int i = 0; i < 4; i++) {
        int r = row0 + ty * 4 + i;
        if (r >= Mr) continue;
        float rs = rowScale ? rowScale[r] : 1.f;
#pragma unroll
        for (int j = 0; j < 4; j++) {
            int cc = col0 + tx * 4 + j;
            if (cc >= Nc) continue;
            float v = acc[i][j] * rs;
            if (addC) v += C[(size_t)r * ldc + cc];
            if (bias) v += bias[cc];
            C[(size_t)r * ldc + cc] = v;
        }
    }
}

// ---------------- self attention on 50 cluster tokens -----------------------
__global__ void sa_kernel() {
    __shared__ float qrow[DIM], sc[MCLUS], pr[MCLUS];
    int i = blockIdx.x, c = threadIdx.x;
    qrow[c] = g_qkv[(size_t)i * 768 + c];
    __syncthreads();
    if (c < MCLUS) {
        float s = 0.f;
        for (int k = 0; k < DIM; k++) s += qrow[k] * g_qkv[(size_t)c * 768 + 256 + k];
        sc[c] = s * SCALE;
    }
    __syncthreads();
    float m = -1e30f;
    for (int t = 0; t < MCLUS; t++) m = fmaxf(m, sc[t]);
    if (c < MCLUS) pr[c] = expf(sc[c] - m);
    __syncthreads();
    float sum = 0.f;
    for (int t = 0; t < MCLUS; t++) sum += pr[t];
    float o = 0.f;
    for (int t = 0; t < MCLUS; t++) o += pr[t] * g_qkv[(size_t)t * 768 + 512 + c];
    g_osc[i * DIM + c] = o / sum;
}

// ---------------- cross: path queries vs cluster keys (65536 x 50) ----------
// kc and vc resident in shared; 64 rows per block.
__global__ void cap_kernel() {
    extern __shared__ float sm[];
    float* kc = sm;                       // 50*257
    float* vc = sm + 12850;               // 50*257
    float* qrow = sm + 25700;             // 256
    float* sc = sm + 25956;               // 64
    float* pr = sm + 26020;               // 64
    int c = threadIdx.x;
    for (int idx = c; idx < MCLUS * DIM; idx += 256) {
        int t = idx >> 8, cc = idx & 255;
        kc[t * 257 + cc] = g_qkv[(size_t)t * 768 + 256 + cc];
        vc[t * 257 + cc] = g_qkv[(size_t)t * 768 + 512 + cc];
    }
    __syncthreads();
    for (int r = 0; r < 64; r++) {
        int gi = blockIdx.x * 64 + r;          // path row
        qrow[c] = g_qkv[(size_t)(MCLUS + gi) * 768 + c];
        __syncthreads();
        if (c < MCLUS) {
            float s = 0.f;
            for (int k = 0; k < DIM; k++) s += qrow[k] * kc[c * 257 + k];
            sc[c] = s * SCALE;
        }
        __syncthreads();
        float m = -1e30f;
        for (int t = 0; t < MCLUS; t++) m = fmaxf(m, sc[t]);
        if (c < MCLUS) pr[c] = expf(sc[c] - m);
        __syncthreads();
        float sum = 0.f;
        for (int t = 0; t < MCLUS; t++) sum += pr[t];
        float o = 0.f;
        for (int t = 0; t < MCLUS; t++) o += pr[t] * vc[t * 257 + c];
        g_ocp[(size_t)gi * DIM + c] = o / sum;
        __syncthreads();
    }
}

// ---------------- cross: cluster queries vs path keys (50 x 65536), split-K --
__global__ void cac_partial() {
    extern __shared__ float sm[];
    float* ks = sm;            // 32*257
    float* vs = sm + 8224;     // 32*257
    float* qrow = sm + 16448;  // 256
    float* sc = sm + 16704;    // 32
    float* pe = sm + 16736;    // 32
    int c = threadIdx.x;
    int i = blockIdx.y;        // query row 0..49
    int split = blockIdx.x;    // 0..15
    int base = split * 4096;
    qrow[c] = g_qkv[(size_t)i * 768 + c];
    float m = -1e30f, l = 0.f, acc = 0.f;
    for (int t0 = 0; t0 < 4096; t0 += 32) {
        __syncthreads();
        for (int idx = c; idx < 32 * DIM; idx += 256) {
            int t = idx >> 8, cc = idx & 255;
            size_t row = (size_t)(MCLUS + base + t0 + t) * 768;
            ks[t * 257 + cc] = g_qkv[row + 256 + cc];
            vs[t * 257 + cc] = g_qkv[row + 512 + cc];
        }
        __syncthreads();
        if (c < 32) {
            float s = 0.f;
            for (int k = 0; k < DIM; k++) s += qrow[k] * ks[c * 257 + k];
            sc[c] = s * SCALE;
        }
        __syncthreads();
        float mnew = m;
        for (int t = 0; t < 32; t++) mnew = fmaxf(mnew, sc[t]);
        if (c < 32) pe[c] = expf(sc[c] - mnew);
        __syncthreads();
        float corr = expf(m - mnew);
        float psum = 0.f, av = 0.f;
        for (int t = 0; t < 32; t++) {
            float e = pe[t];
            psum += e;
            av += e * vs[t * 257 + c];
        }
        acc = acc * corr + av;
        l = l * corr + psum;
        m = mnew;
    }
    int slot = i * 16 + split;
    if (c == 0) { g_cacM[slot] = m; g_cacL[slot] = l; }
    g_cacAcc[(size_t)slot * DIM + c] = acc;
}

__global__ void cac_combine() {
    int i = blockIdx.x, c = threadIdx.x;
    float gm = -1e30f;
    for (int s = 0; s < 16; s++) gm = fmaxf(gm, g_cacM[i * 16 + s]);
    float L = 0.f, o = 0.f;
    for (int s = 0; s < 16; s++) {
        float w = expf(g_cacM[i * 16 + s] - gm);
        L += g_cacL[i * 16 + s] * w;
        o += g_cacAcc[(size_t)(i * 16 + s) * DIM + c] * w;
    }
    g_occ[i * DIM + c] = o / L;
}

// ---------------- linear-attn feature maps ql, kl ---------------------------
__global__ void linprep_kernel(const float* __restrict__ scale_linear) {
    int i = blockIdx.x, c = threadIdx.x;
    size_t tok = (size_t)(MCLUS + i) * 768;
    float sp = logf(1.f + expf(scale_linear[c]));
    float q = g_qkv[tok + c];
    float k = g_qkv[tok + 256 + c];
    float tq = (fmaxf(q, 0.f) + 1e-6f) / sp;
    float tk = (fmaxf(k, 0.f) + 1e-6f) / sp;
    float uq = tq * tq * tq, uk = tk * tk * tk;
    __shared__ float4 red[256];
    red[c] = make_float4(tq * tq, uq * uq, tk * tk, uk * uk);
    __syncthreads();
    for (int s = 128; s > 0; s >>= 1) {
        if (c < s) {
            float4 a = red[c], b = red[c + s];
            red[c] = make_float4(a.x + b.x, a.y + b.y, a.z + b.z, a.w + b.w);
        }
        __syncthreads();
    }
    float4 t = red[0];
    g_ql[(size_t)i * DIM + c] = uq * sqrtf(t.x) / sqrtf(t.y);
    g_kl[(size_t)i * DIM + c] = uk * sqrtf(t.z) / sqrtf(t.w);
}

__global__ void klsum_kernel() {
    int c = threadIdx.x;
    int r0 = blockIdx.x * (NPATH / 64);
    float s = 0.f;
    for (int r = r0; r < r0 + NPATH / 64; r++) s += g_kl[(size_t)r * DIM + c];
    atomicAdd(&g_klsum[c], s);
}

__global__ void zfac_kernel() {
    int warp = threadIdx.x >> 5, lane = threadIdx.x & 31;
    int row = blockIdx.x * 8 + warp;
    float s = 0.f;
    for (int cc = lane; cc < DIM; cc += 32) s += g_ql[(size_t)row * DIM + cc] * g_klsum[cc];
    for (int o = 16; o; o >>= 1) s += __shfl_down_sync(0xffffffffu, s, o);
    if (!lane) g_zfac[row] = 1.f / (s + 1e-6f);
}

// ---------------- kv = kl^T @ vp (256x256), split-K with atomics ------------
__global__ void kv_kernel() {
    __shared__ float As[16][65];
    __shared__ float Bs[16][65];
    int tid = threadIdx.x;
    int tx = tid & 15, ty = tid >> 4;
    int c0 = blockIdx.y * 64, d0 = blockIdx.x * 64;
    int base = blockIdx.z * (NPATH / 32);   // 2048 rows per split
    float acc[4][4];
#pragma unroll
    for (int i = 0; i < 4; i++)
#pragma unroll
        for (int j = 0; j < 4; j++) acc[i][j] = 0.f;
    int lr = tid >> 4;            // 0..15
    int lc = (tid & 15) * 4;      // 0..60
    for (int j0 = 0; j0 < NPATH / 32; j0 += 16) {
        int j = base + j0 + lr;
        float4 av = *(const float4*)&g_kl[(size_t)j * DIM + c0 + lc];
        As[lr][lc + 0] = av.x; As[lr][lc + 1] = av.y; As[lr][lc + 2] = av.z; As[lr][lc + 3] = av.w;
        float4 bv = *(const float4*)&g_qkv[(size_t)(MCLUS + j) * 768 + 512 + d0 + lc];
        Bs[lr][lc + 0] = bv.x; Bs[lr][lc + 1] = bv.y; Bs[lr][lc + 2] = bv.z; Bs[lr][lc + 3] = bv.w;
        __syncthreads();
#pragma unroll
        for (int kk = 0; kk < 16; kk++) {
            float ra[4], rb[4];
#pragma unroll
            for (int i = 0; i < 4; i++) ra[i] = As[kk][ty * 4 + i];
#pragma unroll
            for (int j2 = 0; j2 < 4; j2++) rb[j2] = Bs[kk][tx * 4 + j2];
#pragma unroll
            for (int i = 0; i < 4; i++)
#pragma unroll
                for (int j2 = 0; j2 < 4; j2++) acc[i][j2] += ra[i] * rb[j2];
        }
        __syncthreads();
    }
#pragma unroll
    for (int i = 0; i < 4; i++)
#pragma unroll
        for (int j2 = 0; j2 < 4; j2++)
            atomicAdd(&g_kv[(c0 + ty * 4 + i) * DIM + d0 + tx * 4 + j2], acc[i][j2]);
}

// ---------------- depthwise 5x5 conv over vp as 256x256 image ---------------
// 8 h-consecutive pixels per block, thread = channel. Writes fm into g_spin.
__global__ void conv_kernel(const float* __restrict__ dwc_w,
                            const float* __restrict__ dwc_b) {
    int d = threadIdx.x;
    int b = blockIdx.x;
    int w = b >> 5;
    int h0 = (b & 31) * 8;
    float wt[25];
#pragma unroll
    for (int i = 0; i < 25; i++) wt[i] = dwc_w[d * 25 + i];
    float bias = dwc_b[d];
    float acc[8];
#pragma unroll
    for (int o = 0; o < 8; o++) acc[o] = bias;
#pragma unroll
    for (int a = 0; a < 5; a++) {
        int wa = w + a - 2;
        if ((unsigned)wa >= 256u) continue;
#pragma unroll
        for (int hh = 0; hh < 12; hh++) {
            int hb = h0 - 2 + hh;
            if ((unsigned)hb >= 256u) continue;
            float val = g_qkv[(size_t)(MCLUS + wa * 256 + hb) * 768 + 512 + d];
#pragma unroll
            for (int o = 0; o < 8; o++) {
                int bo = hh - o;           // kernel w-offset
                if (bo >= 0 && bo < 5) acc[o] += val * wt[a * 5 + bo];
            }
        }
    }
#pragma unroll
    for (int o = 0; o < 8; o++)
        g_spin[(size_t)(w * 256 + h0 + o) * DIM + d] = acc[o];
}

// ---------------- gated scorer: A = (tanh(tWa+ba)*sig(tWb+bb))@Wc + bc ------
__global__ void gated_kernel(const float* __restrict__ T, int nrows,
                             const float* __restrict__ Wa, const float* __restrict__ ba,
                             const float* __restrict__ Wb, const float* __restrict__ bb,
                             const float* __restrict__ Wc, const float* __restrict__ bcp,
                             float* __restrict__ Aout)
{
    __shared__ float ts[16 * DIM];
    int c = threadIdx.x;
    int row0 = blockIdx.x * 16;
#pragma unroll
    for (int r = 0; r < 16; r++)
        ts[r * DIM + c] = (row0 + r < nrows) ? T[(size_t)(row0 + r) * DIM + c] : 0.f;
    __syncthreads();
    float aa[16], gg[16];
    float bav = ba[c], bbv = bb[c];
#pragma unroll
    for (int r = 0; r < 16; r++) { aa[r] = bav; gg[r] = bbv; }
    for (int k = 0; k < DIM; k++) {
        float wa = Wa[k * DIM + c];
        float wb = Wb[k * DIM + c];
#pragma unroll
        for (int r = 0; r < 16; r++) {
            float t = ts[r * DIM + k];
            aa[r] += t * wa;
            gg[r] += t * wb;
        }
    }
    float wcv = Wc[c];
    __syncthreads();
#pragma unroll
    for (int r = 0; r < 16; r++) {
        float a = tanhf(aa[r]);
        float g = 1.f / (1.f + expf(-gg[r]));
        ts[r * DIM + c] = a * g * wcv;
    }
    __syncthreads();
    int wid = c >> 5, lane = c & 31;
    float bcv = bcp[0];
    for (int r = wid; r < 16; r += 8) {
        float s = 0.f;
        for (int cc = lane; cc < DIM; cc += 32) s += ts[r * DIM + cc];
#pragma unroll
        for (int o = 16; o; o >>= 1) s += __shfl_down_sync(0xffffffffu, s, o);
        if (!lane && row0 + r < nrows) Aout[row0 + r] = s + bcv;
    }
}

// ---------------- fusion: softmax-weighted pooling + MLP --------------------
__global__ void fmax_kernel(const float* __restrict__ A, int n, int slot) {
    __shared__ float red[256];
    int t = threadIdx.x;
    float m = -1e30f;
    for (int r = t; r < n; r += 256) m = fmaxf(m, A[r]);
    red[t] = m;
    __syncthreads();
    for (int s = 128; s > 0; s >>= 1) {
        if (t < s) red[t] = fmaxf(red[t], red[t + s]);
        __syncthreads();
    }
    if (!t) g_fmax[slot] = red[0];
}

__global__ void wsum_kernel(const float* __restrict__ A, const float* __restrict__ X,
                            int n, int slot, int rpb) {
    __shared__ float se[256];
    int c = threadIdx.x;
    int start = blockIdx.x * rpb;
    int end = min(n, start + rpb);
    float mx = g_fmax[slot];
    float h = 0.f, lpart = 0.f;
    for (int r0 = start; r0 < end; r0 += 256) {
        int cnt = min(256, end - r0);
        if (c < cnt) se[c] = expf(A[r0 + c] - mx);
        __syncthreads();
        for (int t = 0; t < cnt; t++) h += se[t] * X[(size_t)(r0 + t) * DIM + c];
        if (c == 0) for (int t = 0; t < cnt; t++) lpart += se[t];
        __syncthreads();
    }
    atomicAdd(&g_fh[slot * DIM + c], h);
    if (c == 0) atomicAdd(&g_fl[slot], lpart);
}

__global__ void fuse_final(const float* __restrict__ W1, const float* __restrict__ b1,
                           const float* __restrict__ W2, const float* __restrict__ b2,
                           const float* __restrict__ W3a, const float* __restrict__ b3a,
                           const float* __restrict__ W3b, const float* __restrict__ b3b,
                           float* __restrict__ out)
{
    __shared__ float v0[DIM], v1[DIM], hb2[2 * DIM], ub[DIM];
    int f = blockIdx.x;            // 0=cross, 1=self
    int c = threadIdx.x;
    int s0 = f * 2, s1 = f * 2 + 1;
    v0[c] = g_fh[s0 * DIM + c] / g_fl[s0];
    v1[c] = g_fh[s1 * DIM + c] / g_fl[s1];
    __syncthreads();
    float h1 = b1[c], h2 = b2[c];
    for (int k = 0; k < DIM; k++) {
        h1 += v0[k] * W1[k * DIM + c];
        h2 += v1[k] * W2[k * DIM + c];
    }
    hb2[c] = fmaxf(h1, 0.f);
    hb2[DIM + c] = fmaxf(h2, 0.f);
    __syncthreads();
    float u = b3a[c];
    for (int k = 0; k < 2 * DIM; k++) u += hb2[k] * W3a[k * DIM + c];
    ub[c] = fmaxf(u, 0.f);
    __syncthreads();
    float o = b3b[c];
    for (int k = 0; k < DIM; k++) o += ub[k] * W3b[k * DIM + c];
    out[f * DIM + c] = fmaxf(o, 0.f);
}

// ---------------------------------------------------------------------------
extern "C" void kernel_launch(void* const* d_in, const int* in_sizes, int n_in,
                              void* d_out, int out_size) {
    const float* x   = (const float*)d_in[0];
    const float* Wqkv= (const float*)d_in[1];
    const float* scl = (const float*)d_in[2];
    const float* dwcw= (const float*)d_in[3];
    const float* dwcb= (const float*)d_in[4];
    const float* Wa  = (const float*)d_in[5];
    const float* ba  = (const float*)d_in[6];
    const float* Wb  = (const float*)d_in[7];
    const float* bb  = (const float*)d_in[8];
    const float* Wc  = (const float*)d_in[9];
    const float* bc  = (const float*)d_in[10];
    const float* W1  = (const float*)d_in[11];
    const float* b1  = (const float*)d_in[12];
    const float* W2  = (const float*)d_in[13];
    const float* b2  = (const float*)d_in[14];
    const float* W3a = (const float*)d_in[15];
    const float* b3a = (const float*)d_in[16];
    const float* W3b = (const float*)d_in[17];
    const float* b3b = (const float*)d_in[18];
    const float* Wf  = (const float*)d_in[19];
    const float* bf  = (const float*)d_in[20];
    float* out = (float*)d_out;

    cudaFuncSetAttribute(cap_kernel, cudaFuncAttributeMaxDynamicSharedMemorySize, 104448);
    cudaFuncSetAttribute(cac_partial, cudaFuncAttributeMaxDynamicSharedMemorySize, 69632);

    float *p_qkv, *p_ql, *p_kv, *p_spin, *p_osp, *p_zfac;
    float *p_ocp, *p_occ, *p_osc, *p_Acp, *p_Asp, *p_Acc, *p_Asc;
    cudaGetSymbolAddress((void**)&p_qkv, g_qkv);
    cudaGetSymbolAddress((void**)&p_ql,  g_ql);
    cudaGetSymbolAddress((void**)&p_kv,  g_kv);
    cudaGetSymbolAddress((void**)&p_spin,g_spin);
    cudaGetSymbolAddress((void**)&p_osp, g_osp);
    cudaGetSymbolAddress((void**)&p_zfac,g_zfac);
    cudaGetSymbolAddress((void**)&p_ocp, g_ocp);
    cudaGetSymbolAddress((void**)&p_occ, g_occ);
    cudaGetSymbolAddress((void**)&p_osc, g_osc);
    cudaGetSymbolAddress((void**)&p_Acp, g_Acp);
    cudaGetSymbolAddress((void**)&p_Asp, g_Asp);
    cudaGetSymbolAddress((void**)&p_Acc, g_Acc);
    cudaGetSymbolAddress((void**)&p_Asc, g_Asc);

    init_kernel<<<1, 256>>>();

    // qkv = x @ W_qkv
    gemm_kernel<<<dim3(12, 1025), 256>>>(x, 256, Wqkv, 768, p_qkv, 768,
                                         NTOK, 768, 256, nullptr, nullptr, 0);

    // attentions involving cluster tokens
    sa_kernel<<<MCLUS, 256>>>();
    cap_kernel<<<1024, 256, 104448>>>();
    cac_partial<<<dim3(16, MCLUS), 256, 69632>>>();
    cac_combine<<<MCLUS, 256>>>();

    // linear attention path
    linprep_kernel<<<NPATH, 256>>>(scl);
    klsum_kernel<<<64, 256>>>();
    zfac_kernel<<<NPATH / 8, 256>>>();
    kv_kernel<<<dim3(4, 4, 32), 256>>>();

    // depthwise conv -> g_spin (fm), then out_s*zfac added, then @Wf+bf
    conv_kernel<<<8192, 256>>>(dwcw, dwcb);
    gemm_kernel<<<dim3(4, 1024), 256>>>(p_ql, 256, p_kv, 256, p_spin, 256,
                                        NPATH, 256, 256, nullptr, p_zfac, 1);
    gemm_kernel<<<dim3(4, 1024), 256>>>(p_spin, 256, Wf, 256, p_osp, 256,
                                        NPATH, 256, 256, bf, nullptr, 0);

    // gated scorers
    gated_kernel<<<4, 256>>>(p_occ, MCLUS, Wa, ba, Wb, bb, Wc, bc, p_Acc);
    gated_kernel<<<NPATH / 16, 256>>>(p_ocp, NPATH, Wa, ba, Wb, bb, Wc, bc, p_Acp);
    gated_kernel<<<4, 256>>>(p_osc, MCLUS, Wa, ba, Wb, bb, Wc, bc, p_Asc);
    gated_kernel<<<NPATH / 16, 256>>>(p_osp, NPATH, Wa, ba, Wb, bb, Wc, bc, p_Asp);

    // fusion pooling
    fmax_kernel<<<1, 256>>>(p_Acc, MCLUS, 0);
    fmax_kernel<<<1, 256>>>(p_Acp, NPATH, 1);
    fmax_kernel<<<1, 256>>>(p_Asc, MCLUS, 2);
    fmax_kernel<<<1, 256>>>(p_Asp, NPATH, 3);
    wsum_kernel<<<1, 256>>>(p_Acc, p_occ, MCLUS, 0, MCLUS);
    wsum_kernel<<<64, 256>>>(p_Acp, p_ocp, NPATH, 1, 1024);
    wsum_kernel<<<1, 256>>>(p_Asc, p_osc, MCLUS, 2, MCLUS);
    wsum_kernel<<<64, 256>>>(p_Asp, p_osp, NPATH, 3, 1024);

    fuse_final<<<2, 256>>>(W1, b1, W2, b2, W3a, b3a, W3b, b3b, out);
}

// round 3
// speedup vs baseline: 1.7292x; 1.7292x over previous
#include <cuda_runtime.h>
#include <math.h>
#include <stdint.h>

#define NTOK   65586
#define MCLUS  50
#define NPATH  65536
#define DIM    256
#define SCALE  0.0625f   // D^-0.5 = 1/16

// ---------------- scratch (device globals; no allocation allowed) -----------
__device__ float g_qkv[(size_t)NTOK * 768];      // q|k|v per token row
__device__ float g_ocp[(size_t)NPATH * DIM];     // out_cross_path
__device__ float g_osc[MCLUS * DIM];             // out_self_celltypes
__device__ float g_occ[MCLUS * DIM];             // out_cross_celltypes (numerator, then result)
__device__ float g_ql[(size_t)NPATH * DIM];      // ql; later reused as aa scratch
__device__ float g_kl[(size_t)NPATH * DIM];      // kl; later reused as gg scratch
__device__ float g_klsum[DIM];
__device__ float g_kv[DIM * DIM];
__device__ float g_zfac[NPATH];
__device__ float g_spin[(size_t)NPATH * DIM];    // fm, then out_s+fm
__device__ float g_osp[(size_t)NPATH * DIM];     // out_self_path
__device__ float g_Scap[(size_t)NPATH * 64];     // cap scores -> P
__device__ float g_Scac[(size_t)NPATH * 64];     // cac scores -> E
__device__ float g_pmax[64 * 64];
__device__ float g_cmax[64];
__device__ float g_clsum[64];
__device__ float g_Acp[NPATH];
__device__ float g_Asp[NPATH];
__device__ float g_Acc[MCLUS];
__device__ float g_Asc[MCLUS];
__device__ float g_fmax[4];
__device__ float g_fl[4];
__device__ float g_fh[4 * DIM];

// ---------------- init: zero accumulators used with atomics -----------------
__global__ void init_kernel() {
    int t = threadIdx.x;
    for (int i = t; i < DIM * DIM; i += 256) g_kv[i] = 0.f;
    for (int i = t; i < MCLUS * DIM; i += 256) g_occ[i] = 0.f;
    if (t < DIM) g_klsum[t] = 0.f;
    if (t < 64) g_clsum[t] = 0.f;
    if (t < 4) g_fl[t] = 0.f;
    for (int i = t; i < 4 * DIM; i += 256) g_fh[i] = 0.f;
}

// ============================================================================
// TF32 tensor-core GEMM (3xTF32 split for fp32-class accuracy)
// C[M,N] = A @ B  (+bias[n]) (*rowScale[m]) (+C) (or atomicAdd into C)
// transA: A given as Aphys[k][m] (lda = phys row stride)
// transB: B given as Bphys[n][k] (ldb = phys row stride), valid n rows < nBound
// Block tile 128x128x16, 8 warps of 64x32.
// ============================================================================
#define BM 128
#define BN 128
#define BK 16

__device__ __forceinline__ void mma_tf32(float* c, const unsigned* a, const unsigned* b) {
    asm volatile(
        "mma.sync.aligned.m16n8k8.row.col.f32.tf32.tf32.f32 "
        "{%0,%1,%2,%3},{%4,%5,%6,%7},{%8,%9},{%0,%1,%2,%3};\n"
        : "+f"(c[0]), "+f"(c[1]), "+f"(c[2]), "+f"(c[3])
        : "r"(a[0]), "r"(a[1]), "r"(a[2]), "r"(a[3]), "r"(b[0]), "r"(b[1]));
}

__device__ __forceinline__ void split_tf32(float v, float& hi, float& lo) {
    unsigned h;
    asm("cvt.rna.tf32.f32 %0, %1;" : "=r"(h) : "f"(v));
    hi = __uint_as_float(h);
    lo = v - hi;
}

__global__ void __launch_bounds__(256) tf32gemm(
    const float* __restrict__ A, int lda, int transA,
    const float* __restrict__ B, int ldb, int transB,
    float* __restrict__ C, int ldc,
    int M, int N, int kBase, int kRange,
    const float* __restrict__ bias,
    const float* __restrict__ rowScale,
    int addC, int atomicOut, int nBound)
{
    __shared__ float As_hi[128][17], As_lo[128][17];
    __shared__ float Bs_hi[16][132], Bs_lo[16][132];

    int tid = threadIdx.x;
    int w = tid >> 5, lane = tid & 31;
    int wm = w >> 2, wn = w & 3;          // warps 2 (m) x 4 (n)
    int g = lane >> 2, tig = lane & 3;

    int m0 = blockIdx.y * BM;
    int n0 = blockIdx.x * BN;
    int k0beg = kBase + blockIdx.z * kRange;
    int k0end = k0beg + kRange;

    float acc[4][4][4];
#pragma unroll
    for (int i = 0; i < 4; i++)
#pragma unroll
        for (int j = 0; j < 4; j++)
#pragma unroll
            for (int q = 0; q < 4; q++) acc[i][j][q] = 0.f;

    for (int k0 = k0beg; k0 < k0end; k0 += BK) {
        __syncthreads();
        // ---- stage A ----
        if (!transA) {
            int kk = tid & 15, rbase = tid >> 4;
#pragma unroll
            for (int e = 0; e < 8; e++) {
                int r = rbase + 16 * e;
                int gm = m0 + r;
                float v = (gm < M) ? A[(size_t)gm * lda + k0 + kk] : 0.f;
                float h, l; split_tf32(v, h, l);
                As_hi[r][kk] = h; As_lo[r][kk] = l;
            }
        } else {
            int rb = tid & 31, kb = tid >> 5;
#pragma unroll
            for (int e = 0; e < 8; e++) {
                int kk = kb + 8 * (e & 1);
                int r = rb + 32 * (e >> 1);
                int gm = m0 + r;
                float v = (gm < M) ? A[(size_t)(k0 + kk) * lda + gm] : 0.f;
                float h, l; split_tf32(v, h, l);
                As_hi[r][kk] = h; As_lo[r][kk] = l;
            }
        }
        // ---- stage B ----
        if (!transB) {
            int cb = tid & 31, kb = tid >> 5;
#pragma unroll
            for (int e = 0; e < 8; e++) {
                int c = cb + 32 * (e & 3);
                int kk = kb + 8 * (e >> 2);
                float v = (n0 + c < N) ? B[(size_t)(k0 + kk) * ldb + n0 + c] : 0.f;
                float h, l; split_tf32(v, h, l);
                Bs_hi[kk][c] = h; Bs_lo[kk][c] = l;
            }
        } else {
            int kk = tid & 15, cb = tid >> 4;
#pragma unroll
            for (int e = 0; e < 8; e++) {
                int c = cb + 16 * e;
                float v = (n0 + c < nBound) ? B[(size_t)(n0 + c) * ldb + k0 + kk] : 0.f;
                float h, l; split_tf32(v, h, l);
                Bs_hi[kk][c] = h; Bs_lo[kk][c] = l;
            }
        }
        __syncthreads();

#pragma unroll
        for (int ks = 0; ks < 2; ks++) {
            int kof = ks * 8;
            unsigned ah[4][4], al[4][4], bh[4][2], bl[4][2];
#pragma unroll
            for (int mt = 0; mt < 4; mt++) {
                int mb = wm * 64 + mt * 16;
                ah[mt][0] = __float_as_uint(As_hi[mb + g][kof + tig]);
                ah[mt][1] = __float_as_uint(As_hi[mb + g + 8][kof + tig]);
                ah[mt][2] = __float_as_uint(As_hi[mb + g][kof + tig + 4]);
                ah[mt][3] = __float_as_uint(As_hi[mb + g + 8][kof + tig + 4]);
                al[mt][0] = __float_as_uint(As_lo[mb + g][kof + tig]);
                al[mt][1] = __float_as_uint(As_lo[mb + g + 8][kof + tig]);
                al[mt][2] = __float_as_uint(As_lo[mb + g][kof + tig + 4]);
                al[mt][3] = __float_as_uint(As_lo[mb + g + 8][kof + tig + 4]);
            }
#pragma unroll
            for (int nt = 0; nt < 4; nt++) {
                int nb = wn * 32 + nt * 8;
                bh[nt][0] = __float_as_uint(Bs_hi[kof + tig][nb + g]);
                bh[nt][1] = __float_as_uint(Bs_hi[kof + tig + 4][nb + g]);
                bl[nt][0] = __float_as_uint(Bs_lo[kof + tig][nb + g]);
                bl[nt][1] = __float_as_uint(Bs_lo[kof + tig + 4][nb + g]);
            }
#pragma unroll
            for (int mt = 0; mt < 4; mt++)
#pragma unroll
                for (int nt = 0; nt < 4; nt++) {
                    mma_tf32(acc[mt][nt], ah[mt], bh[nt]);
                    mma_tf32(acc[mt][nt], al[mt], bh[nt]);
                    mma_tf32(acc[mt][nt], ah[mt], bl[nt]);
                }
        }
    }

    // ---- epilogue ----
#pragma unroll
    for (int mt = 0; mt < 4; mt++) {
#pragma unroll
        for (int nt = 0; nt < 4; nt++) {
            int rA = m0 + wm * 64 + mt * 16 + g;
            int cA = n0 + wn * 32 + nt * 8 + tig * 2;
#pragma unroll
            for (int q = 0; q < 4; q++) {
                int r = rA + (q >= 2 ? 8 : 0);
                int c = cA + (q & 1);
                if (r >= M || c >= N) continue;
                float v = acc[mt][nt][q];
                if (atomicOut) {
                    atomicAdd(&C[(size_t)r * ldc + c], v);
                } else {
                    if (rowScale) v *= rowScale[r];
                    if (addC) v += C[(size_t)r * ldc + c];
                    if (bias) v += bias[c];
                    C[(size_t)r * ldc + c] = v;
                }
            }
        }
    }
}

// ---------------- self attention on 50 cluster tokens -----------------------
__global__ void sa_kernel() {
    __shared__ float qrow[DIM], sc[MCLUS], pr[MCLUS];
    int i = blockIdx.x, c = threadIdx.x;
    qrow[c] = g_qkv[(size_t)i * 768 + c];
    __syncthreads();
    if (c < MCLUS) {
        float s = 0.f;
        for (int k = 0; k < DIM; k++) s += qrow[k] * g_qkv[(size_t)c * 768 + 256 + k];
        sc[c] = s * SCALE;
    }
    __syncthreads();
    float m = -1e30f;
    for (int t = 0; t < MCLUS; t++) m = fmaxf(m, sc[t]);
    if (c < MCLUS) pr[c] = expf(sc[c] - m);
    __syncthreads();
    float sum = 0.f;
    for (int t = 0; t < MCLUS; t++) sum += pr[t];
    float o = 0.f;
    for (int t = 0; t < MCLUS; t++) o += pr[t] * g_qkv[(size_t)t * 768 + 512 + c];
    g_osc[i * DIM + c] = o / sum;
}

// ---------------- cap: row softmax over 50 cluster scores (in place) --------
__global__ void cap_rowsoft() {
    int row = blockIdx.x * 8 + (threadIdx.x >> 5);
    int lane = threadIdx.x & 31;
    size_t base = (size_t)row * 64;
    float v1 = (lane < MCLUS) ? g_Scap[base + lane] : -1e30f;
    float v2 = (lane + 32 < MCLUS) ? g_Scap[base + 32 + lane] : -1e30f;
    float m = fmaxf(v1, v2);
#pragma unroll
    for (int o = 16; o; o >>= 1) m = fmaxf(m, __shfl_xor_sync(0xffffffffu, m, o));
    float e1 = (lane < MCLUS) ? expf((v1 - m) * SCALE) : 0.f;
    float e2 = (lane + 32 < MCLUS) ? expf((v2 - m) * SCALE) : 0.f;
    float s = e1 + e2;
#pragma unroll
    for (int o = 16; o; o >>= 1) s += __shfl_xor_sync(0xffffffffu, s, o);
    float inv = 1.f / s;
    g_Scap[base + lane] = e1 * inv;
    g_Scap[base + 32 + lane] = e2 * inv;
}

// ---------------- cac: column max / exp / column sums -----------------------
__global__ void colmax_part() {
    int col = threadIdx.x & 63, rq = threadIdx.x >> 6;
    float m = -1e30f;
    int r0 = blockIdx.x * 1024;
    for (int r = r0 + rq; r < r0 + 1024; r += 4) m = fmaxf(m, g_Scac[(size_t)r * 64 + col]);
    __shared__ float sm[256];
    sm[threadIdx.x] = m;
    __syncthreads();
    if (rq == 0)
        g_pmax[blockIdx.x * 64 + col] =
            fmaxf(fmaxf(sm[col], sm[64 + col]), fmaxf(sm[128 + col], sm[192 + col]));
}

__global__ void colmax_comb() {
    int col = threadIdx.x;
    float m = -1e30f;
    for (int b = 0; b < 64; b++) m = fmaxf(m, g_pmax[b * 64 + col]);
    g_cmax[col] = m;
}

__global__ void cac_exp() {
    int col = threadIdx.x & 63, rq = threadIdx.x >> 6;
    float mx = g_cmax[col];
    float s = 0.f;
    int r0 = blockIdx.x * 1024;
    for (int r = r0 + rq; r < r0 + 1024; r += 4) {
        float v = g_Scac[(size_t)r * 64 + col];
        float e = (col < MCLUS) ? expf((v - mx) * SCALE) : 0.f;
        g_Scac[(size_t)r * 64 + col] = e;
        s += e;
    }
    __shared__ float sm[256];
    sm[threadIdx.x] = s;
    __syncthreads();
    if (rq == 0 && col < MCLUS)
        atomicAdd(&g_clsum[col], sm[col] + sm[64 + col] + sm[128 + col] + sm[192 + col]);
}

__global__ void cac_div() {
    int i = blockIdx.x, c = threadIdx.x;
    g_occ[i * DIM + c] /= g_clsum[i];
}

// ---------------- linear-attn feature maps ql, kl ---------------------------
__global__ void linprep_kernel(const float* __restrict__ scale_linear) {
    int i = blockIdx.x, c = threadIdx.x;
    size_t tok = (size_t)(MCLUS + i) * 768;
    float sp = logf(1.f + expf(scale_linear[c]));
    float q = g_qkv[tok + c];
    float k = g_qkv[tok + 256 + c];
    float tq = (fmaxf(q, 0.f) + 1e-6f) / sp;
    float tk = (fmaxf(k, 0.f) + 1e-6f) / sp;
    float uq = tq * tq * tq, uk = tk * tk * tk;
    __shared__ float4 red[256];
    red[c] = make_float4(tq * tq, uq * uq, tk * tk, uk * uk);
    __syncthreads();
    for (int s = 128; s > 0; s >>= 1) {
        if (c < s) {
            float4 a = red[c], b = red[c + s];
            red[c] = make_float4(a.x + b.x, a.y + b.y, a.z + b.z, a.w + b.w);
        }
        __syncthreads();
    }
    float4 t = red[0];
    g_ql[(size_t)i * DIM + c] = uq * sqrtf(t.x) / sqrtf(t.y);
    g_kl[(size_t)i * DIM + c] = uk * sqrtf(t.z) / sqrtf(t.w);
}

__global__ void klsum_kernel() {
    int c = threadIdx.x;
    int r0 = blockIdx.x * (NPATH / 64);
    float s = 0.f;
    for (int r = r0; r < r0 + NPATH / 64; r++) s += g_kl[(size_t)r * DIM + c];
    atomicAdd(&g_klsum[c], s);
}

__global__ void zfac_kernel() {
    int warp = threadIdx.x >> 5, lane = threadIdx.x & 31;
    int row = blockIdx.x * 8 + warp;
    float s = 0.f;
    for (int cc = lane; cc < DIM; cc += 32) s += g_ql[(size_t)row * DIM + cc] * g_klsum[cc];
    for (int o = 16; o; o >>= 1) s += __shfl_down_sync(0xffffffffu, s, o);
    if (!lane) g_zfac[row] = 1.f / (s + 1e-6f);
}

// ---------------- depthwise 5x5 conv over vp as 256x256 image ---------------
__global__ void conv_kernel(const float* __restrict__ dwc_w,
                            const float* __restrict__ dwc_b) {
    int d = threadIdx.x;
    int b = blockIdx.x;
    int w = b >> 5;
    int h0 = (b & 31) * 8;
    float wt[25];
#pragma unroll
    for (int i = 0; i < 25; i++) wt[i] = dwc_w[d * 25 + i];
    float bias = dwc_b[d];
    float acc[8];
#pragma unroll
    for (int o = 0; o < 8; o++) acc[o] = bias;
#pragma unroll
    for (int a = 0; a < 5; a++) {
        int wa = w + a - 2;
        if ((unsigned)wa >= 256u) continue;
#pragma unroll
        for (int hh = 0; hh < 12; hh++) {
            int hb = h0 - 2 + hh;
            if ((unsigned)hb >= 256u) continue;
            float val = g_qkv[(size_t)(MCLUS + wa * 256 + hb) * 768 + 512 + d];
#pragma unroll
            for (int o = 0; o < 8; o++) {
                int bo = hh - o;
                if (bo >= 0 && bo < 5) acc[o] += val * wt[a * 5 + bo];
            }
        }
    }
#pragma unroll
    for (int o = 0; o < 8; o++)
        g_spin[(size_t)(w * 256 + h0 + o) * DIM + d] = acc[o];
}

// ---------------- gated scorer (small, 50-row tensors) ----------------------
__global__ void gated_kernel(const float* __restrict__ T, int nrows,
                             const float* __restrict__ Wa, const float* __restrict__ ba,
                             const float* __restrict__ Wb, const float* __restrict__ bb,
                             const float* __restrict__ Wc, const float* __restrict__ bcp,
                             float* __restrict__ Aout)
{
    __shared__ float ts[16 * DIM];
    int c = threadIdx.x;
    int row0 = blockIdx.x * 16;
#pragma unroll
    for (int r = 0; r < 16; r++)
        ts[r * DIM + c] = (row0 + r < nrows) ? T[(size_t)(row0 + r) * DIM + c] : 0.f;
    __syncthreads();
    float aa[16], gg[16];
    float bav = ba[c], bbv = bb[c];
#pragma unroll
    for (int r = 0; r < 16; r++) { aa[r] = bav; gg[r] = bbv; }
    for (int k = 0; k < DIM; k++) {
        float wa = Wa[k * DIM + c];
        float wb = Wb[k * DIM + c];
#pragma unroll
        for (int r = 0; r < 16; r++) {
            float t = ts[r * DIM + k];
            aa[r] += t * wa;
            gg[r] += t * wb;
        }
    }
    float wcv = Wc[c];
    __syncthreads();
#pragma unroll
    for (int r = 0; r < 16; r++) {
        float a = tanhf(aa[r]);
        float g = 1.f / (1.f + expf(-gg[r]));
        ts[r * DIM + c] = a * g * wcv;
    }
    __syncthreads();
    int wid = c >> 5, lane = c & 31;
    float bcv = bcp[0];
    for (int r = wid; r < 16; r += 8) {
        float s = 0.f;
        for (int cc = lane; cc < DIM; cc += 32) s += ts[r * DIM + cc];
#pragma unroll
        for (int o = 16; o; o >>= 1) s += __shfl_down_sync(0xffffffffu, s, o);
        if (!lane && row0 + r < nrows) Aout[row0 + r] = s + bcv;
    }
}

// ---------------- gated reduce (big tensors, aa/gg precomputed by GEMM) -----
__global__ void gated_reduce(const float* __restrict__ aa, const float* __restrict__ gg,
                             const float* __restrict__ Wc, const float* __restrict__ bcp,
                             float* __restrict__ Aout)
{
    int row = blockIdx.x * 8 + (threadIdx.x >> 5);
    int lane = threadIdx.x & 31;
    size_t base = (size_t)row * DIM;
    float s = 0.f;
    for (int c = lane; c < DIM; c += 32) {
        float a = tanhf(aa[base + c]);
        float g = 1.f / (1.f + expf(-gg[base + c]));
        s += a * g * Wc[c];
    }
#pragma unroll
    for (int o = 16; o; o >>= 1) s += __shfl_down_sync(0xffffffffu, s, o);
    if (!lane) Aout[row] = s + bcp[0];
}

// ---------------- fusion: softmax-weighted pooling + MLP --------------------
__global__ void fmax_kernel(const float* __restrict__ A, int n, int slot) {
    __shared__ float red[256];
    int t = threadIdx.x;
    float m = -1e30f;
    for (int r = t; r < n; r += 256) m = fmaxf(m, A[r]);
    red[t] = m;
    __syncthreads();
    for (int s = 128; s > 0; s >>= 1) {
        if (t < s) red[t] = fmaxf(red[t], red[t + s]);
        __syncthreads();
    }
    if (!t) g_fmax[slot] = red[0];
}

__global__ void wsum_kernel(const float* __restrict__ A, const float* __restrict__ X,
                            int n, int slot, int rpb) {
    __shared__ float se[256];
    int c = threadIdx.x;
    int start = blockIdx.x * rpb;
    int end = min(n, start + rpb);
    float mx = g_fmax[slot];
    float h = 0.f, lpart = 0.f;
    for (int r0 = start; r0 < end; r0 += 256) {
        int cnt = min(256, end - r0);
        if (c < cnt) se[c] = expf(A[r0 + c] - mx);
        __syncthreads();
        for (int t = 0; t < cnt; t++) h += se[t] * X[(size_t)(r0 + t) * DIM + c];
        if (c == 0) for (int t = 0; t < cnt; t++) lpart += se[t];
        __syncthreads();
    }
    atomicAdd(&g_fh[slot * DIM + c], h);
    if (c == 0) atomicAdd(&g_fl[slot], lpart);
}

__global__ void fuse_final(const float* __restrict__ W1, const float* __restrict__ b1,
                           const float* __restrict__ W2, const float* __restrict__ b2,
                           const float* __restrict__ W3a, const float* __restrict__ b3a,
                           const float* __restrict__ W3b, const float* __restrict__ b3b,
                           float* __restrict__ out)
{
    __shared__ float v0[DIM], v1[DIM], hb2[2 * DIM], ub[DIM];
    int f = blockIdx.x;
    int c = threadIdx.x;
    int s0 = f * 2, s1 = f * 2 + 1;
    v0[c] = g_fh[s0 * DIM + c] / g_fl[s0];
    v1[c] = g_fh[s1 * DIM + c] / g_fl[s1];
    __syncthreads();
    float h1 = b1[c], h2 = b2[c];
    for (int k = 0; k < DIM; k++) {
        h1 += v0[k] * W1[k * DIM + c];
        h2 += v1[k] * W2[k * DIM + c];
    }
    hb2[c] = fmaxf(h1, 0.f);
    hb2[DIM + c] = fmaxf(h2, 0.f);
    __syncthreads();
    float u = b3a[c];
    for (int k = 0; k < 2 * DIM; k++) u += hb2[k] * W3a[k * DIM + c];
    ub[c] = fmaxf(u, 0.f);
    __syncthreads();
    float o = b3b[c];
    for (int k = 0; k < DIM; k++) o += ub[k] * W3b[k * DIM + c];
    out[f * DIM + c] = fmaxf(o, 0.f);
}

// ---------------------------------------------------------------------------
extern "C" void kernel_launch(void* const* d_in, const int* in_sizes, int n_in,
                              void* d_out, int out_size) {
    const float* x   = (const float*)d_in[0];
    const float* Wqkv= (const float*)d_in[1];
    const float* scl = (const float*)d_in[2];
    const float* dwcw= (const float*)d_in[3];
    const float* dwcb= (const float*)d_in[4];
    const float* Wa  = (const float*)d_in[5];
    const float* ba  = (const float*)d_in[6];
    const float* Wb  = (const float*)d_in[7];
    const float* bb  = (const float*)d_in[8];
    const float* Wc  = (const float*)d_in[9];
    const float* bc  = (const float*)d_in[10];
    const float* W1  = (const float*)d_in[11];
    const float* b1  = (const float*)d_in[12];
    const float* W2  = (const float*)d_in[13];
    const float* b2  = (const float*)d_in[14];
    const float* W3a = (const float*)d_in[15];
    const float* b3a = (const float*)d_in[16];
    const float* W3b = (const float*)d_in[17];
    const float* b3b = (const float*)d_in[18];
    const float* Wf  = (const float*)d_in[19];
    const float* bf  = (const float*)d_in[20];
    float* out = (float*)d_out;

    float *p_qkv, *p_ql, *p_kl, *p_kv, *p_spin, *p_osp, *p_zfac;
    float *p_ocp, *p_occ, *p_osc, *p_Acp, *p_Asp, *p_Acc, *p_Asc, *p_Scap, *p_Scac;
    cudaGetSymbolAddress((void**)&p_qkv, g_qkv);
    cudaGetSymbolAddress((void**)&p_ql,  g_ql);
    cudaGetSymbolAddress((void**)&p_kl,  g_kl);
    cudaGetSymbolAddress((void**)&p_kv,  g_kv);
    cudaGetSymbolAddress((void**)&p_spin,g_spin);
    cudaGetSymbolAddress((void**)&p_osp, g_osp);
    cudaGetSymbolAddress((void**)&p_zfac,g_zfac);
    cudaGetSymbolAddress((void**)&p_ocp, g_ocp);
    cudaGetSymbolAddress((void**)&p_occ, g_occ);
    cudaGetSymbolAddress((void**)&p_osc, g_osc);
    cudaGetSymbolAddress((void**)&p_Acp, g_Acp);
    cudaGetSymbolAddress((void**)&p_Asp, g_Asp);
    cudaGetSymbolAddress((void**)&p_Acc, g_Acc);
    cudaGetSymbolAddress((void**)&p_Asc, g_Asc);
    cudaGetSymbolAddress((void**)&p_Scap, g_Scap);
    cudaGetSymbolAddress((void**)&p_Scac, g_Scac);

    init_kernel<<<1, 256>>>();

    // qkv = x @ W_qkv  (65586 x 768 x 256)
    tf32gemm<<<dim3(6, 513), 256>>>(x, 256, 0, Wqkv, 768, 0, p_qkv, 768,
                                    NTOK, 768, 0, 256, nullptr, nullptr, 0, 0, 0);

    sa_kernel<<<MCLUS, 256>>>();

    // ---- cap: S = qp @ kc^T ; softmax rows; ocp = P @ vc ----
    tf32gemm<<<dim3(1, 512), 256>>>(p_qkv + (size_t)MCLUS * 768, 768, 0,
                                    p_qkv + 256, 768, 1, p_Scap, 64,
                                    NPATH, 64, 0, 256, nullptr, nullptr, 0, 0, MCLUS);
    cap_rowsoft<<<NPATH / 8, 256>>>();
    tf32gemm<<<dim3(2, 512), 256>>>(p_Scap, 64, 0,
                                    p_qkv + 512, 768, 0, p_ocp, 256,
                                    NPATH, 256, 0, 64, nullptr, nullptr, 0, 0, 0);

    // ---- cac: S2 = kp @ qc^T ; colmax/exp/colsum ; occ = E^T @ vp / l ----
    tf32gemm<<<dim3(1, 512), 256>>>(p_qkv + (size_t)MCLUS * 768 + 256, 768, 0,
                                    p_qkv, 768, 1, p_Scac, 64,
                                    NPATH, 64, 0, 256, nullptr, nullptr, 0, 0, MCLUS);
    colmax_part<<<64, 256>>>();
    colmax_comb<<<1, 64>>>();
    cac_exp<<<64, 256>>>();
    tf32gemm<<<dim3(2, 1, 32), 256>>>(p_Scac, 64, 1,
                                      p_qkv + (size_t)MCLUS * 768 + 512, 768, 0, p_occ, 256,
                                      MCLUS, 256, 0, 2048, nullptr, nullptr, 0, 1, 0);
    cac_div<<<MCLUS, 256>>>();

    // ---- linear attention path ----
    linprep_kernel<<<NPATH, 256>>>(scl);
    klsum_kernel<<<64, 256>>>();
    zfac_kernel<<<NPATH / 8, 256>>>();
    // kv = kl^T @ vp  (256x256, K=65536 split 32, atomic)
    tf32gemm<<<dim3(2, 2, 32), 256>>>(p_kl, 256, 1,
                                      p_qkv + (size_t)MCLUS * 768 + 512, 768, 0, p_kv, 256,
                                      256, 256, 0, 2048, nullptr, nullptr, 0, 1, 0);

    conv_kernel<<<8192, 256>>>(dwcw, dwcb);
    // spin = zfac * (ql @ kv) + fm
    tf32gemm<<<dim3(2, 512), 256>>>(p_ql, 256, 0, p_kv, 256, 0, p_spin, 256,
                                    NPATH, 256, 0, 256, nullptr, p_zfac, 1, 0, 0);
    // osp = spin @ Wf + bf
    tf32gemm<<<dim3(2, 512), 256>>>(p_spin, 256, 0, Wf, 256, 0, p_osp, 256,
                                    NPATH, 256, 0, 256, bf, nullptr, 0, 0, 0);

    // ---- gated scorers ----
    gated_kernel<<<4, 256>>>(p_occ, MCLUS, Wa, ba, Wb, bb, Wc, bc, p_Acc);
    gated_kernel<<<4, 256>>>(p_osc, MCLUS, Wa, ba, Wb, bb, Wc, bc, p_Asc);

    // big gated via tensor cores (g_ql/g_kl free after out_s)
    tf32gemm<<<dim3(2, 512), 256>>>(p_ocp, 256, 0, Wa, 256, 0, p_ql, 256,
                                    NPATH, 256, 0, 256, ba, nullptr, 0, 0, 0);
    tf32gemm<<<dim3(2, 512), 256>>>(p_ocp, 256, 0, Wb, 256, 0, p_kl, 256,
                                    NPATH, 256, 0, 256, bb, nullptr, 0, 0, 0);
    gated_reduce<<<NPATH / 8, 256>>>(p_ql, p_kl, Wc, bc, p_Acp);

    tf32gemm<<<dim3(2, 512), 256>>>(p_osp, 256, 0, Wa, 256, 0, p_ql, 256,
                                    NPATH, 256, 0, 256, ba, nullptr, 0, 0, 0);
    tf32gemm<<<dim3(2, 512), 256>>>(p_osp, 256, 0, Wb, 256, 0, p_kl, 256,
                                    NPATH, 256, 0, 256, bb, nullptr, 0, 0, 0);
    gated_reduce<<<NPATH / 8, 256>>>(p_ql, p_kl, Wc, bc, p_Asp);

    // ---- fusion pooling ----
    fmax_kernel<<<1, 256>>>(p_Acc, MCLUS, 0);
    fmax_kernel<<<1, 256>>>(p_Acp, NPATH, 1);
    fmax_kernel<<<1, 256>>>(p_Asc, MCLUS, 2);
    fmax_kernel<<<1, 256>>>(p_Asp, NPATH, 3);
    wsum_kernel<<<1, 256>>>(p_Acc, p_occ, MCLUS, 0, MCLUS);
    wsum_kernel<<<64, 256>>>(p_Acp, p_ocp, NPATH, 1, 1024);
    wsum_kernel<<<1, 256>>>(p_Asc, p_osc, MCLUS, 2, MCLUS);
    wsum_kernel<<<64, 256>>>(p_Asp, p_osp, NPATH, 3, 1024);

    fuse_final<<<2, 256>>>(W1, b1, W2, b2, W3a, b3a, W3b, b3b, out);
}

// round 4
// speedup vs baseline: 1.7307x; 1.0009x over previous
#include <cuda_runtime.h>
#include <math.h>
#include <stdint.h>

#define NTOK   65586
#define MCLUS  50
#define NPATH  65536
#define DIM    256
#define SCALE  0.0625f   // D^-0.5 = 1/16

// ---------------- scratch (device globals; no allocation allowed) -----------
__device__ float g_qkv[(size_t)NTOK * 768];      // q|k|v per token row
__device__ float g_ocp[(size_t)NPATH * DIM];     // out_cross_path
__device__ float g_osc[MCLUS * DIM];             // out_self_celltypes
__device__ float g_occ[MCLUS * DIM];             // out_cross_celltypes (numerator, then result)
__device__ float g_ql[(size_t)NPATH * DIM];      // ql; later reused as aa scratch
__device__ float g_kl[(size_t)NPATH * DIM];      // kl; later reused as gg scratch
__device__ float g_klsum[DIM];
__device__ float g_kv[DIM * DIM];
__device__ float g_zfac[NPATH];
__device__ float g_spin[(size_t)NPATH * DIM];    // fm, then out_s+fm
__device__ float g_osp[(size_t)NPATH * DIM];     // out_self_path
__device__ float g_Scap[(size_t)NPATH * 64];     // cap scores -> P
__device__ float g_Scac[(size_t)NPATH * 64];     // cac scores -> E
__device__ float g_pmax[64 * 64];
__device__ float g_cmax[64];
__device__ float g_clsum[64];
__device__ float g_Acp[NPATH];
__device__ float g_Asp[NPATH];
__device__ float g_Acc[MCLUS];
__device__ float g_Asc[MCLUS];
__device__ float g_fmax[4];
__device__ float g_fl[4];
__device__ float g_fh[4 * DIM];

// ---------------- init: zero accumulators used with atomics -----------------
__global__ void init_kernel() {
    int t = threadIdx.x;
    for (int i = t; i < DIM * DIM; i += 256) g_kv[i] = 0.f;
    for (int i = t; i < MCLUS * DIM; i += 256) g_occ[i] = 0.f;
    if (t < DIM) g_klsum[t] = 0.f;
    if (t < 64) g_clsum[t] = 0.f;
    if (t < 4) g_fl[t] = 0.f;
    for (int i = t; i < 4 * DIM; i += 256) g_fh[i] = 0.f;
}

// ============================================================================
// TF32 tensor-core GEMM (3xTF32 split for fp32-class accuracy)
// C[M,N] = A @ B  (+bias[n]) (*rowScale[m]) (+C) (or atomicAdd into C)
// transA: A given as Aphys[k][m] (lda = phys row stride)
// transB: B given as Bphys[n][k] (ldb = phys row stride), valid n rows < nBound
// Block tile 128x128x16, 8 warps of 64x32.
// ============================================================================
#define BM 128
#define BN 128
#define BK 16

__device__ __forceinline__ void mma_tf32(float* c, const unsigned* a, const unsigned* b) {
    asm volatile(
        "mma.sync.aligned.m16n8k8.row.col.f32.tf32.tf32.f32 "
        "{%0,%1,%2,%3},{%4,%5,%6,%7},{%8,%9},{%0,%1,%2,%3};\n"
        : "+f"(c[0]), "+f"(c[1]), "+f"(c[2]), "+f"(c[3])
        : "r"(a[0]), "r"(a[1]), "r"(a[2]), "r"(a[3]), "r"(b[0]), "r"(b[1]));
}

__device__ __forceinline__ void split_tf32(float v, float& hi, float& lo) {
    unsigned h;
    asm("cvt.rna.tf32.f32 %0, %1;" : "=r"(h) : "f"(v));
    hi = __uint_as_float(h);
    lo = v - hi;
}

__global__ void __launch_bounds__(256) tf32gemm(
    const float* __restrict__ A, int lda, int transA,
    const float* __restrict__ B, int ldb, int transB,
    float* __restrict__ C, int ldc,
    int M, int N, int kBase, int kRange,
    const float* __restrict__ bias,
    const float* __restrict__ rowScale,
    int addC, int atomicOut, int nBound)
{
    __shared__ float As_hi[128][17], As_lo[128][17];
    __shared__ float Bs_hi[16][132], Bs_lo[16][132];

    int tid = threadIdx.x;
    int w = tid >> 5, lane = tid & 31;
    int wm = w >> 2, wn = w & 3;          // warps 2 (m) x 4 (n)
    int g = lane >> 2, tig = lane & 3;

    int m0 = blockIdx.y * BM;
    int n0 = blockIdx.x * BN;
    int k0beg = kBase + blockIdx.z * kRange;
    int k0end = k0beg + kRange;

    float acc[4][4][4];
#pragma unroll
    for (int i = 0; i < 4; i++)
#pragma unroll
        for (int j = 0; j < 4; j++)
#pragma unroll
            for (int q = 0; q < 4; q++) acc[i][j][q] = 0.f;

    for (int k0 = k0beg; k0 < k0end; k0 += BK) {
        __syncthreads();
        // ---- stage A ----
        if (!transA) {
            int kk = tid & 15, rbase = tid >> 4;
#pragma unroll
            for (int e = 0; e < 8; e++) {
                int r = rbase + 16 * e;
                int gm = m0 + r;
                float v = (gm < M) ? A[(size_t)gm * lda + k0 + kk] : 0.f;
                float h, l; split_tf32(v, h, l);
                As_hi[r][kk] = h; As_lo[r][kk] = l;
            }
        } else {
            int rb = tid & 31, kb = tid >> 5;
#pragma unroll
            for (int e = 0; e < 8; e++) {
                int kk = kb + 8 * (e & 1);
                int r = rb + 32 * (e >> 1);
                int gm = m0 + r;
                float v = (gm < M) ? A[(size_t)(k0 + kk) * lda + gm] : 0.f;
                float h, l; split_tf32(v, h, l);
                As_hi[r][kk] = h; As_lo[r][kk] = l;
            }
        }
        // ---- stage B ----
        if (!transB) {
            int cb = tid & 31, kb = tid >> 5;
#pragma unroll
            for (int e = 0; e < 8; e++) {
                int c = cb + 32 * (e & 3);
                int kk = kb + 8 * (e >> 2);
                float v = (n0 + c < N) ? B[(size_t)(k0 + kk) * ldb + n0 + c] : 0.f;
                float h, l; split_tf32(v, h, l);
                Bs_hi[kk][c] = h; Bs_lo[kk][c] = l;
            }
        } else {
            int kk = tid & 15, cb = tid >> 4;
#pragma unroll
            for (int e = 0; e < 8; e++) {
                int c = cb + 16 * e;
                float v = (n0 + c < nBound) ? B[(size_t)(n0 + c) * ldb + k0 + kk] : 0.f;
                float h, l; split_tf32(v, h, l);
                Bs_hi[kk][c] = h; Bs_lo[kk][c] = l;
            }
        }
        __syncthreads();

#pragma unroll
        for (int ks = 0; ks < 2; ks++) {
            int kof = ks * 8;
            unsigned ah[4][4], al[4][4], bh[4][2], bl[4][2];
#pragma unroll
            for (int mt = 0; mt < 4; mt++) {
                int mb = wm * 64 + mt * 16;
                ah[mt][0] = __float_as_uint(As_hi[mb + g][kof + tig]);
                ah[mt][1] = __float_as_uint(As_hi[mb + g + 8][kof + tig]);
                ah[mt][2] = __float_as_uint(As_hi[mb + g][kof + tig + 4]);
                ah[mt][3] = __float_as_uint(As_hi[mb + g + 8][kof + tig + 4]);
                al[mt][0] = __float_as_uint(As_lo[mb + g][kof + tig]);
                al[mt][1] = __float_as_uint(As_lo[mb + g + 8][kof + tig]);
                al[mt][2] = __float_as_uint(As_lo[mb + g][kof + tig + 4]);
                al[mt][3] = __float_as_uint(As_lo[mb + g + 8][kof + tig + 4]);
            }
#pragma unroll
            for (int nt = 0; nt < 4; nt++) {
                int nb = wn * 32 + nt * 8;
                bh[nt][0] = __float_as_uint(Bs_hi[kof + tig][nb + g]);
                bh[nt][1] = __float_as_uint(Bs_hi[kof + tig + 4][nb + g]);
                bl[nt][0] = __float_as_uint(Bs_lo[kof + tig][nb + g]);
                bl[nt][1] = __float_as_uint(Bs_lo[kof + tig + 4][nb + g]);
            }
#pragma unroll
            for (int mt = 0; mt < 4; mt++)
#pragma unroll
                for (int nt = 0; nt < 4; nt++) {
                    mma_tf32(acc[mt][nt], ah[mt], bh[nt]);
                    mma_tf32(acc[mt][nt], al[mt], bh[nt]);
                    mma_tf32(acc[mt][nt], ah[mt], bl[nt]);
                }
        }
    }

    // ---- epilogue ----
#pragma unroll
    for (int mt = 0; mt < 4; mt++) {
#pragma unroll
        for (int nt = 0; nt < 4; nt++) {
            int rA = m0 + wm * 64 + mt * 16 + g;
            int cA = n0 + wn * 32 + nt * 8 + tig * 2;
#pragma unroll
            for (int q = 0; q < 4; q++) {
                int r = rA + (q >= 2 ? 8 : 0);
                int c = cA + (q & 1);
                if (r >= M || c >= N) continue;
                float v = acc[mt][nt][q];
                if (atomicOut) {
                    atomicAdd(&C[(size_t)r * ldc + c], v);
                } else {
                    if (rowScale) v *= rowScale[r];
                    if (addC) v += C[(size_t)r * ldc + c];
                    if (bias) v += bias[c];
                    C[(size_t)r * ldc + c] = v;
                }
            }
        }
    }
}

// ---------------- self attention on 50 cluster tokens -----------------------
__global__ void sa_kernel() {
    __shared__ float qrow[DIM], sc[MCLUS], pr[MCLUS];
    int i = blockIdx.x, c = threadIdx.x;
    qrow[c] = g_qkv[(size_t)i * 768 + c];
    __syncthreads();
    if (c < MCLUS) {
        float s = 0.f;
        for (int k = 0; k < DIM; k++) s += qrow[k] * g_qkv[(size_t)c * 768 + 256 + k];
        sc[c] = s * SCALE;
    }
    __syncthreads();
    float m = -1e30f;
    for (int t = 0; t < MCLUS; t++) m = fmaxf(m, sc[t]);
    if (c < MCLUS) pr[c] = expf(sc[c] - m);
    __syncthreads();
    float sum = 0.f;
    for (int t = 0; t < MCLUS; t++) sum += pr[t];
    float o = 0.f;
    for (int t = 0; t < MCLUS; t++) o += pr[t] * g_qkv[(size_t)t * 768 + 512 + c];
    g_osc[i * DIM + c] = o / sum;
}

// ---------------- cap: row softmax over 50 cluster scores (in place) --------
__global__ void cap_rowsoft() {
    int row = blockIdx.x * 8 + (threadIdx.x >> 5);
    int lane = threadIdx.x & 31;
    size_t base = (size_t)row * 64;
    float v1 = (lane < MCLUS) ? g_Scap[base + lane] : -1e30f;
    float v2 = (lane + 32 < MCLUS) ? g_Scap[base + 32 + lane] : -1e30f;
    float m = fmaxf(v1, v2);
#pragma unroll
    for (int o = 16; o; o >>= 1) m = fmaxf(m, __shfl_xor_sync(0xffffffffu, m, o));
    float e1 = (lane < MCLUS) ? expf((v1 - m) * SCALE) : 0.f;
    float e2 = (lane + 32 < MCLUS) ? expf((v2 - m) * SCALE) : 0.f;
    float s = e1 + e2;
#pragma unroll
    for (int o = 16; o; o >>= 1) s += __shfl_xor_sync(0xffffffffu, s, o);
    float inv = 1.f / s;
    g_Scap[base + lane] = e1 * inv;
    g_Scap[base + 32 + lane] = e2 * inv;
}

// ---------------- cac: column max / exp / column sums -----------------------
__global__ void colmax_part() {
    int col = threadIdx.x & 63, rq = threadIdx.x >> 6;
    float m = -1e30f;
    int r0 = blockIdx.x * 1024;
    for (int r = r0 + rq; r < r0 + 1024; r += 4) m = fmaxf(m, g_Scac[(size_t)r * 64 + col]);
    __shared__ float sm[256];
    sm[threadIdx.x] = m;
    __syncthreads();
    if (rq == 0)
        g_pmax[blockIdx.x * 64 + col] =
            fmaxf(fmaxf(sm[col], sm[64 + col]), fmaxf(sm[128 + col], sm[192 + col]));
}

__global__ void colmax_comb() {
    int col = threadIdx.x;
    float m = -1e30f;
    for (int b = 0; b < 64; b++) m = fmaxf(m, g_pmax[b * 64 + col]);
    g_cmax[col] = m;
}

__global__ void cac_exp() {
    int col = threadIdx.x & 63, rq = threadIdx.x >> 6;
    float mx = g_cmax[col];
    float s = 0.f;
    int r0 = blockIdx.x * 1024;
    for (int r = r0 + rq; r < r0 + 1024; r += 4) {
        float v = g_Scac[(size_t)r * 64 + col];
        float e = (col < MCLUS) ? expf((v - mx) * SCALE) : 0.f;
        g_Scac[(size_t)r * 64 + col] = e;
        s += e;
    }
    __shared__ float sm[256];
    sm[threadIdx.x] = s;
    __syncthreads();
    if (rq == 0 && col < MCLUS)
        atomicAdd(&g_clsum[col], sm[col] + sm[64 + col] + sm[128 + col] + sm[192 + col]);
}

__global__ void cac_div() {
    int i = blockIdx.x, c = threadIdx.x;
    g_occ[i * DIM + c] /= g_clsum[i];
}

// ---------------- linear-attn feature maps ql, kl ---------------------------
__global__ void linprep_kernel(const float* __restrict__ scale_linear) {
    int i = blockIdx.x, c = threadIdx.x;
    size_t tok = (size_t)(MCLUS + i) * 768;
    float sp = logf(1.f + expf(scale_linear[c]));
    float q = g_qkv[tok + c];
    float k = g_qkv[tok + 256 + c];
    float tq = (fmaxf(q, 0.f) + 1e-6f) / sp;
    float tk = (fmaxf(k, 0.f) + 1e-6f) / sp;
    float uq = tq * tq * tq, uk = tk * tk * tk;
    __shared__ float4 red[256];
    red[c] = make_float4(tq * tq, uq * uq, tk * tk, uk * uk);
    __syncthreads();
    for (int s = 128; s > 0; s >>= 1) {
        if (c < s) {
            float4 a = red[c], b = red[c + s];
            red[c] = make_float4(a.x + b.x, a.y + b.y, a.z + b.z, a.w + b.w);
        }
        __syncthreads();
    }
    float4 t = red[0];
    g_ql[(size_t)i * DIM + c] = uq * sqrtf(t.x) / sqrtf(t.y);
    g_kl[(size_t)i * DIM + c] = uk * sqrtf(t.z) / sqrtf(t.w);
}

__global__ void klsum_kernel() {
    int c = threadIdx.x;
    int r0 = blockIdx.x * (NPATH / 64);
    float s = 0.f;
    for (int r = r0; r < r0 + NPATH / 64; r++) s += g_kl[(size_t)r * DIM + c];
    atomicAdd(&g_klsum[c], s);
}

__global__ void zfac_kernel() {
    int warp = threadIdx.x >> 5, lane = threadIdx.x & 31;
    int row = blockIdx.x * 8 + warp;
    float s = 0.f;
    for (int cc = lane; cc < DIM; cc += 32) s += g_ql[(size_t)row * DIM + cc] * g_klsum[cc];
    for (int o = 16; o; o >>= 1) s += __shfl_down_sync(0xffffffffu, s, o);
    if (!lane) g_zfac[row] = 1.f / (s + 1e-6f);
}

// ---------------- depthwise 5x5 conv over vp as 256x256 image ---------------
__global__ void conv_kernel(const float* __restrict__ dwc_w,
                            const float* __restrict__ dwc_b) {
    int d = threadIdx.x;
    int b = blockIdx.x;
    int w = b >> 5;
    int h0 = (b & 31) * 8;
    float wt[25];
#pragma unroll
    for (int i = 0; i < 25; i++) wt[i] = dwc_w[d * 25 + i];
    float bias = dwc_b[d];
    float acc[8];
#pragma unroll
    for (int o = 0; o < 8; o++) acc[o] = bias;
#pragma unroll
    for (int a = 0; a < 5; a++) {
        int wa = w + a - 2;
        if ((unsigned)wa >= 256u) continue;
#pragma unroll
        for (int hh = 0; hh < 12; hh++) {
            int hb = h0 - 2 + hh;
            if ((unsigned)hb >= 256u) continue;
            float val = g_qkv[(size_t)(MCLUS + wa * 256 + hb) * 768 + 512 + d];
#pragma unroll
            for (int o = 0; o < 8; o++) {
                int bo = hh - o;
                if (bo >= 0 && bo < 5) acc[o] += val * wt[a * 5 + bo];
            }
        }
    }
#pragma unroll
    for (int o = 0; o < 8; o++)
        g_spin[(size_t)(w * 256 + h0 + o) * DIM + d] = acc[o];
}

// ---------------- gated scorer (small, 50-row tensors) ----------------------
__global__ void gated_kernel(const float* __restrict__ T, int nrows,
                             const float* __restrict__ Wa, const float* __restrict__ ba,
                             const float* __restrict__ Wb, const float* __restrict__ bb,
                             const float* __restrict__ Wc, const float* __restrict__ bcp,
                             float* __restrict__ Aout)
{
    __shared__ float ts[16 * DIM];
    int c = threadIdx.x;
    int row0 = blockIdx.x * 16;
#pragma unroll
    for (int r = 0; r < 16; r++)
        ts[r * DIM + c] = (row0 + r < nrows) ? T[(size_t)(row0 + r) * DIM + c] : 0.f;
    __syncthreads();
    float aa[16], gg[16];
    float bav = ba[c], bbv = bb[c];
#pragma unroll
    for (int r = 0; r < 16; r++) { aa[r] = bav; gg[r] = bbv; }
    for (int k = 0; k < DIM; k++) {
        float wa = Wa[k * DIM + c];
        float wb = Wb[k * DIM + c];
#pragma unroll
        for (int r = 0; r < 16; r++) {
            float t = ts[r * DIM + k];
            aa[r] += t * wa;
            gg[r] += t * wb;
        }
    }
    float wcv = Wc[c];
    __syncthreads();
#pragma unroll
    for (int r = 0; r < 16; r++) {
        float a = tanhf(aa[r]);
        float g = 1.f / (1.f + expf(-gg[r]));
        ts[r * DIM + c] = a * g * wcv;
    }
    __syncthreads();
    int wid = c >> 5, lane = c & 31;
    float bcv = bcp[0];
    for (int r = wid; r < 16; r += 8) {
        float s = 0.f;
        for (int cc = lane; cc < DIM; cc += 32) s += ts[r * DIM + cc];
#pragma unroll
        for (int o = 16; o; o >>= 1) s += __shfl_down_sync(0xffffffffu, s, o);
        if (!lane && row0 + r < nrows) Aout[row0 + r] = s + bcv;
    }
}

// ---------------- gated reduce (big tensors, aa/gg precomputed by GEMM) -----
__global__ void gated_reduce(const float* __restrict__ aa, const float* __restrict__ gg,
                             const float* __restrict__ Wc, const float* __restrict__ bcp,
                             float* __restrict__ Aout)
{
    int row = blockIdx.x * 8 + (threadIdx.x >> 5);
    int lane = threadIdx.x & 31;
    size_t base = (size_t)row * DIM;
    float s = 0.f;
    for (int c = lane; c < DIM; c += 32) {
        float a = tanhf(aa[base + c]);
        float g = 1.f / (1.f + expf(-gg[base + c]));
        s += a * g * Wc[c];
    }
#pragma unroll
    for (int o = 16; o; o >>= 1) s += __shfl_down_sync(0xffffffffu, s, o);
    if (!lane) Aout[row] = s + bcp[0];
}

// ---------------- fusion: softmax-weighted pooling + MLP --------------------
__global__ void fmax_kernel(const float* __restrict__ A, int n, int slot) {
    __shared__ float red[256];
    int t = threadIdx.x;
    float m = -1e30f;
    for (int r = t; r < n; r += 256) m = fmaxf(m, A[r]);
    red[t] = m;
    __syncthreads();
    for (int s = 128; s > 0; s >>= 1) {
        if (t < s) red[t] = fmaxf(red[t], red[t + s]);
        __syncthreads();
    }
    if (!t) g_fmax[slot] = red[0];
}

__global__ void wsum_kernel(const float* __restrict__ A, const float* __restrict__ X,
                            int n, int slot, int rpb) {
    __shared__ float se[256];
    int c = threadIdx.x;
    int start = blockIdx.x * rpb;
    int end = min(n, start + rpb);
    float mx = g_fmax[slot];
    float h = 0.f, lpart = 0.f;
    for (int r0 = start; r0 < end; r0 += 256) {
        int cnt = min(256, end - r0);
        if (c < cnt) se[c] = expf(A[r0 + c] - mx);
        __syncthreads();
        for (int t = 0; t < cnt; t++) h += se[t] * X[(size_t)(r0 + t) * DIM + c];
        if (c == 0) for (int t = 0; t < cnt; t++) lpart += se[t];
        __syncthreads();
    }
    atomicAdd(&g_fh[slot * DIM + c], h);
    if (c == 0) atomicAdd(&g_fl[slot], lpart);
}

__global__ void fuse_final(const float* __restrict__ W1, const float* __restrict__ b1,
                           const float* __restrict__ W2, const float* __restrict__ b2,
                           const float* __restrict__ W3a, const float* __restrict__ b3a,
                           const float* __restrict__ W3b, const float* __restrict__ b3b,
                           float* __restrict__ out)
{
    __shared__ float v0[DIM], v1[DIM], hb2[2 * DIM], ub[DIM];
    int f = blockIdx.x;
    int c = threadIdx.x;
    int s0 = f * 2, s1 = f * 2 + 1;
    v0[c] = g_fh[s0 * DIM + c] / g_fl[s0];
    v1[c] = g_fh[s1 * DIM + c] / g_fl[s1];
    __syncthreads();
    float h1 = b1[c], h2 = b2[c];
    for (int k = 0; k < DIM; k++) {
        h1 += v0[k] * W1[k * DIM + c];
        h2 += v1[k] * W2[k * DIM + c];
    }
    hb2[c] = fmaxf(h1, 0.f);
    hb2[DIM + c] = fmaxf(h2, 0.f);
    __syncthreads();
    float u = b3a[c];
    for (int k = 0; k < 2 * DIM; k++) u += hb2[k] * W3a[k * DIM + c];
    ub[c] = fmaxf(u, 0.f);
    __syncthreads();
    float o = b3b[c];
    for (int k = 0; k < DIM; k++) o += ub[k] * W3b[k * DIM + c];
    out[f * DIM + c] = fmaxf(o, 0.f);
}

// ---------------------------------------------------------------------------
extern "C" void kernel_launch(void* const* d_in, const int* in_sizes, int n_in,
                              void* d_out, int out_size) {
    const float* x   = (const float*)d_in[0];
    const float* Wqkv= (const float*)d_in[1];
    const float* scl = (const float*)d_in[2];
    const float* dwcw= (const float*)d_in[3];
    const float* dwcb= (const float*)d_in[4];
    const float* Wa  = (const float*)d_in[5];
    const float* ba  = (const float*)d_in[6];
    const float* Wb  = (const float*)d_in[7];
    const float* bb  = (const float*)d_in[8];
    const float* Wc  = (const float*)d_in[9];
    const float* bc  = (const float*)d_in[10];
    const float* W1  = (const float*)d_in[11];
    const float* b1  = (const float*)d_in[12];
    const float* W2  = (const float*)d_in[13];
    const float* b2  = (const float*)d_in[14];
    const float* W3a = (const float*)d_in[15];
    const float* b3a = (const float*)d_in[16];
    const float* W3b = (const float*)d_in[17];
    const float* b3b = (const float*)d_in[18];
    const float* Wf  = (const float*)d_in[19];
    const float* bf  = (const float*)d_in[20];
    float* out = (float*)d_out;

    float *p_qkv, *p_ql, *p_kl, *p_kv, *p_spin, *p_osp, *p_zfac;
    float *p_ocp, *p_occ, *p_osc, *p_Acp, *p_Asp, *p_Acc, *p_Asc, *p_Scap, *p_Scac;
    cudaGetSymbolAddress((void**)&p_qkv, g_qkv);
    cudaGetSymbolAddress((void**)&p_ql,  g_ql);
    cudaGetSymbolAddress((void**)&p_kl,  g_kl);
    cudaGetSymbolAddress((void**)&p_kv,  g_kv);
    cudaGetSymbolAddress((void**)&p_spin,g_spin);
    cudaGetSymbolAddress((void**)&p_osp, g_osp);
    cudaGetSymbolAddress((void**)&p_zfac,g_zfac);
    cudaGetSymbolAddress((void**)&p_ocp, g_ocp);
    cudaGetSymbolAddress((void**)&p_occ, g_occ);
    cudaGetSymbolAddress((void**)&p_osc, g_osc);
    cudaGetSymbolAddress((void**)&p_Acp, g_Acp);
    cudaGetSymbolAddress((void**)&p_Asp, g_Asp);
    cudaGetSymbolAddress((void**)&p_Acc, g_Acc);
    cudaGetSymbolAddress((void**)&p_Asc, g_Asc);
    cudaGetSymbolAddress((void**)&p_Scap, g_Scap);
    cudaGetSymbolAddress((void**)&p_Scac, g_Scac);

    init_kernel<<<1, 256>>>();

    // qkv = x @ W_qkv  (65586 x 768 x 256)
    tf32gemm<<<dim3(6, 513), 256>>>(x, 256, 0, Wqkv, 768, 0, p_qkv, 768,
                                    NTOK, 768, 0, 256, nullptr, nullptr, 0, 0, 0);

    sa_kernel<<<MCLUS, 256>>>();

    // ---- cap: S = qp @ kc^T ; softmax rows; ocp = P @ vc ----
    tf32gemm<<<dim3(1, 512), 256>>>(p_qkv + (size_t)MCLUS * 768, 768, 0,
                                    p_qkv + 256, 768, 1, p_Scap, 64,
                                    NPATH, 64, 0, 256, nullptr, nullptr, 0, 0, MCLUS);
    cap_rowsoft<<<NPATH / 8, 256>>>();
    tf32gemm<<<dim3(2, 512), 256>>>(p_Scap, 64, 0,
                                    p_qkv + 512, 768, 0, p_ocp, 256,
                                    NPATH, 256, 0, 64, nullptr, nullptr, 0, 0, 0);

    // ---- cac: S2 = kp @ qc^T ; colmax/exp/colsum ; occ = E^T @ vp / l ----
    tf32gemm<<<dim3(1, 512), 256>>>(p_qkv + (size_t)MCLUS * 768 + 256, 768, 0,
                                    p_qkv, 768, 1, p_Scac, 64,
                                    NPATH, 64, 0, 256, nullptr, nullptr, 0, 0, MCLUS);
    colmax_part<<<64, 256>>>();
    colmax_comb<<<1, 64>>>();
    cac_exp<<<64, 256>>>();
    tf32gemm<<<dim3(2, 1, 32), 256>>>(p_Scac, 64, 1,
                                      p_qkv + (size_t)MCLUS * 768 + 512, 768, 0, p_occ, 256,
                                      MCLUS, 256, 0, 2048, nullptr, nullptr, 0, 1, 0);
    cac_div<<<MCLUS, 256>>>();

    // ---- linear attention path ----
    linprep_kernel<<<NPATH, 256>>>(scl);
    klsum_kernel<<<64, 256>>>();
    zfac_kernel<<<NPATH / 8, 256>>>();
    // kv = kl^T @ vp  (256x256, K=65536 split 32, atomic)
    tf32gemm<<<dim3(2, 2, 32), 256>>>(p_kl, 256, 1,
                                      p_qkv + (size_t)MCLUS * 768 + 512, 768, 0, p_kv, 256,
                                      256, 256, 0, 2048, nullptr, nullptr, 0, 1, 0);

    conv_kernel<<<8192, 256>>>(dwcw, dwcb);
    // spin = zfac * (ql @ kv) + fm
    tf32gemm<<<dim3(2, 512), 256>>>(p_ql, 256, 0, p_kv, 256, 0, p_spin, 256,
                                    NPATH, 256, 0, 256, nullptr, p_zfac, 1, 0, 0);
    // osp = spin @ Wf + bf
    tf32gemm<<<dim3(2, 512), 256>>>(p_spin, 256, 0, Wf, 256, 0, p_osp, 256,
                                    NPATH, 256, 0, 256, bf, nullptr, 0, 0, 0);

    // ---- gated scorers ----
    gated_kernel<<<4, 256>>>(p_occ, MCLUS, Wa, ba, Wb, bb, Wc, bc, p_Acc);
    gated_kernel<<<4, 256>>>(p_osc, MCLUS, Wa, ba, Wb, bb, Wc, bc, p_Asc);

    // big gated via tensor cores (g_ql/g_kl free after out_s)
    tf32gemm<<<dim3(2, 512), 256>>>(p_ocp, 256, 0, Wa, 256, 0, p_ql, 256,
                                    NPATH, 256, 0, 256, ba, nullptr, 0, 0, 0);
    tf32gemm<<<dim3(2, 512), 256>>>(p_ocp, 256, 0, Wb, 256, 0, p_kl, 256,
                                    NPATH, 256, 0, 256, bb, nullptr, 0, 0, 0);
    gated_reduce<<<NPATH / 8, 256>>>(p_ql, p_kl, Wc, bc, p_Acp);

    tf32gemm<<<dim3(2, 512), 256>>>(p_osp, 256, 0, Wa, 256, 0, p_ql, 256,
                                    NPATH, 256, 0, 256, ba, nullptr, 0, 0, 0);
    tf32gemm<<<dim3(2, 512), 256>>>(p_osp, 256, 0, Wb, 256, 0, p_kl, 256,
                                    NPATH, 256, 0, 256, bb, nullptr, 0, 0, 0);
    gated_reduce<<<NPATH / 8, 256>>>(p_ql, p_kl, Wc, bc, p_Asp);

    // ---- fusion pooling ----
    fmax_kernel<<<1, 256>>>(p_Acc, MCLUS, 0);
    fmax_kernel<<<1, 256>>>(p_Acp, NPATH, 1);
    fmax_kernel<<<1, 256>>>(p_Asc, MCLUS, 2);
    fmax_kernel<<<1, 256>>>(p_Asp, NPATH, 3);
    wsum_kernel<<<1, 256>>>(p_Acc, p_occ, MCLUS, 0, MCLUS);
    wsum_kernel<<<64, 256>>>(p_Acp, p_ocp, NPATH, 1, 1024);
    wsum_kernel<<<1, 256>>>(p_Asc, p_osc, MCLUS, 2, MCLUS);
    wsum_kernel<<<64, 256>>>(p_Asp, p_osp, NPATH, 3, 1024);

    fuse_final<<<2, 256>>>(W1, b1, W2, b2, W3a, b3a, W3b, b3b, out);
}